// round 4
// baseline (speedup 1.0000x reference)
#include <cuda_runtime.h>
#include <cstdint>

#define D_MODEL     2048
#define NUM_EXPERTS 64
#define TOP_K       4
#define TM          128              // tokens per CTA
#define KC          32               // K chunk (fp32 elems)
#define NCHUNK      (D_MODEL / KC)   // 64
#define N_TOKENS    16384
#define NBLK        (N_TOKENS / TM)  // 128
#define MAXREP      16384
#define GAP_EPS     1e-5f

// ---- dynamic smem layout (bytes) ----
#define US_STAGE   (128 * 36 * 4)               // 18432
#define B_STAGE    (64 * 36 * 4)                // 9216
#define SM_US      0                            // 2 stages: 36864
#define SM_BHI     (2 * US_STAGE)               // 36864
#define SM_BLO     (SM_BHI + 2 * B_STAGE)       // 55296
#define SM_BIAS    (SM_BLO + 2 * B_STAGE)       // 73728
#define SM_TOTAL   (SM_BIAS + 256)              // 73984
// epilogue L[128][65] floats reuses [0, 33280) (inside uS region)

// ---- device scratch (no allocations allowed) ----
__device__ float g_expert_partial[NBLK * NUM_EXPERTS];
__device__ float g_ET_hi[NUM_EXPERTS * D_MODEL];   // E^T, tf32-hi as fp32 bits
__device__ float g_ET_lo[NUM_EXPERTS * D_MODEL];   // E^T, tf32-lo
__device__ int   g_count;
__device__ int   g_repair[MAXREP];

// ================= helpers ==================================================
__device__ __forceinline__ uint32_t smem_to_u32(const void* p) {
    uint32_t a;
    asm("{ .reg .u64 t; cvta.to.shared.u64 t, %1; cvt.u32.u64 %0, t; }" : "=r"(a) : "l"(p));
    return a;
}
__device__ __forceinline__ uint32_t f2tf32(float x) {
    uint32_t r;
    asm("cvt.rna.tf32.f32 %0, %1;" : "=r"(r) : "f"(x));
    return r;
}
#define CP_ASYNC16(dst_u32, src_ptr) \
    asm volatile("cp.async.cg.shared.global [%0], [%1], 16;" :: "r"(dst_u32), "l"(src_ptr))
#define CP_COMMIT() asm volatile("cp.async.commit_group;" ::: "memory")
#define CP_WAIT1()  asm volatile("cp.async.wait_group 1;" ::: "memory")
#define CP_WAIT0()  asm volatile("cp.async.wait_group 0;" ::: "memory")

// m16n8k8 tf32 mma: D += A*B, row.col, fp32 acc
__device__ __forceinline__ void mma_tf32(float* d, const uint32_t a[4], uint32_t b0, uint32_t b1) {
    asm volatile(
        "mma.sync.aligned.m16n8k8.row.col.f32.tf32.tf32.f32 "
        "{%0,%1,%2,%3}, {%4,%5,%6,%7}, {%8,%9}, {%0,%1,%2,%3};"
        : "+f"(d[0]), "+f"(d[1]), "+f"(d[2]), "+f"(d[3])
        : "r"(a[0]), "r"(a[1]), "r"(a[2]), "r"(a[3]), "r"(b0), "r"(b1));
}

// ================= prep: E[2048][64] -> E^T tf32 hi/lo; zero repair count ====
__global__ void prep_E(const float* __restrict__ E) {
    __shared__ float t[64][65];
    const int tid = threadIdx.x;
    const int k0 = blockIdx.x * 64;
    if (blockIdx.x == 0 && tid == 0) g_count = 0;
#pragma unroll
    for (int i = 0; i < 16; i++) {
        int idx = tid + i * 256;
        int r = idx >> 6, c = idx & 63;          // r: k-offset, c: expert
        t[r][c] = E[(size_t)(k0 + r) * NUM_EXPERTS + c];
    }
    __syncthreads();
#pragma unroll
    for (int i = 0; i < 16; i++) {
        int idx = tid + i * 256;
        int n = idx >> 6, kk = idx & 63;
        float v = t[kk][n];
        uint32_t hu = f2tf32(v);
        float hf = __uint_as_float(hu);
        uint32_t lu = f2tf32(v - hf);
        g_ET_hi[(size_t)n * D_MODEL + k0 + kk] = __uint_as_float(hu);
        g_ET_lo[(size_t)n * D_MODEL + k0 + kk] = __uint_as_float(lu);
    }
}

// ================= main fused router (tensor-core fast path) ================
__global__ void __launch_bounds__(256) router_kernel(
    const float* __restrict__ u, const float* __restrict__ bias,
    float* __restrict__ out_idx, float* __restrict__ out_val,
    float* __restrict__ out_scores)
{
    extern __shared__ char smem[];
    const uint32_t sb = smem_to_u32(smem);
    const int tid = threadIdx.x, wid = tid >> 5, lid = tid & 31;
    const int tokBase = blockIdx.x * TM;

    if (tid < NUM_EXPERTS) ((float*)(smem + SM_BIAS))[tid] = bias[tid];

    const int urow = tid >> 3;      // 0..31
    const int uc4  = tid & 7;       // float4 within 32-float row
    auto issue = [&](int c) {
        const int st = c & 1;
        const int k0 = c * KC;
        const uint32_t usb = sb + SM_US + st * US_STAGE;
        const uint32_t bhb = sb + SM_BHI + st * B_STAGE;
        const uint32_t blb = sb + SM_BLO + st * B_STAGE;
#pragma unroll
        for (int i = 0; i < 4; i++) {
            int row = urow + i * 32;
            CP_ASYNC16(usb + (uint32_t)(row * 36 + uc4 * 4) * 4,
                       u + (size_t)(tokBase + row) * D_MODEL + k0 + uc4 * 4);
        }
#pragma unroll
        for (int i = 0; i < 2; i++) {
            int idx = tid + i * 256;
            int n = idx >> 3, c4 = idx & 7;
            CP_ASYNC16(bhb + (uint32_t)(n * 36 + c4 * 4) * 4,
                       g_ET_hi + (size_t)n * D_MODEL + k0 + c4 * 4);
            CP_ASYNC16(blb + (uint32_t)(n * 36 + c4 * 4) * 4,
                       g_ET_lo + (size_t)n * D_MODEL + k0 + c4 * 4);
        }
        CP_COMMIT();
    };

    float acc[8][4];
#pragma unroll
    for (int nt = 0; nt < 8; nt++)
#pragma unroll
        for (int j = 0; j < 4; j++) acc[nt][j] = 0.f;

    const int g = lid >> 2, tig = lid & 3;
    const int r0 = wid * 16 + g;

    issue(0);
    issue(1);

    for (int c = 0; c < NCHUNK; c++) {
        if (c < NCHUNK - 1) CP_WAIT1(); else CP_WAIT0();
        __syncthreads();

        const int st = c & 1;
        const float* us = (const float*)(smem + SM_US + st * US_STAGE);
        const float* bh = (const float*)(smem + SM_BHI + st * B_STAGE);
        const float* bl = (const float*)(smem + SM_BLO + st * B_STAGE);

#pragma unroll
        for (int ks = 0; ks < 4; ks++) {
            const int kk = ks * 8;
            float a0 = us[r0 * 36 + kk + tig];
            float a1 = us[(r0 + 8) * 36 + kk + tig];
            float a2 = us[r0 * 36 + kk + tig + 4];
            float a3 = us[(r0 + 8) * 36 + kk + tig + 4];
            uint32_t ahi[4], alo[4];
            ahi[0] = f2tf32(a0); alo[0] = f2tf32(a0 - __uint_as_float(ahi[0]));
            ahi[1] = f2tf32(a1); alo[1] = f2tf32(a1 - __uint_as_float(ahi[1]));
            ahi[2] = f2tf32(a2); alo[2] = f2tf32(a2 - __uint_as_float(ahi[2]));
            ahi[3] = f2tf32(a3); alo[3] = f2tf32(a3 - __uint_as_float(ahi[3]));
#pragma unroll
            for (int nt = 0; nt < 8; nt++) {
                const int n = nt * 8 + g;
                uint32_t bh0 = __float_as_uint(bh[n * 36 + kk + tig]);
                uint32_t bh1 = __float_as_uint(bh[n * 36 + kk + tig + 4]);
                uint32_t bl0 = __float_as_uint(bl[n * 36 + kk + tig]);
                uint32_t bl1 = __float_as_uint(bl[n * 36 + kk + tig + 4]);
                mma_tf32(acc[nt], ahi, bh0, bh1);
                mma_tf32(acc[nt], ahi, bl0, bl1);
                mma_tf32(acc[nt], alo, bh0, bh1);
            }
        }
        __syncthreads();
        if (c + 2 < NCHUNK) issue(c + 2);
    }

    // ---- epilogue: D -> smem L[128][65], softmax + top-5 gap test + top-4 ----
    float* L = (float*)(smem + SM_US);  // 33280 B fits in the 2 u-stages
#pragma unroll
    for (int nt = 0; nt < 8; nt++) {
        const int cb = nt * 8 + tig * 2;
        L[r0 * 65 + cb]           = acc[nt][0];
        L[r0 * 65 + cb + 1]       = acc[nt][1];
        L[(r0 + 8) * 65 + cb]     = acc[nt][2];
        L[(r0 + 8) * 65 + cb + 1] = acc[nt][3];
    }
    __syncthreads();

    const float* biasS = (const float*)(smem + SM_BIAS);
    if (tid < TM) {
        const int t = tid;
        float p[64];
        float mx = -1e30f;
#pragma unroll
        for (int e = 0; e < 64; e++) { p[e] = L[t * 65 + e] + biasS[e]; mx = fmaxf(mx, p[e]); }
        float s = 0.f;
#pragma unroll
        for (int e = 0; e < 64; e++) { p[e] = expf(p[e] - mx); s += p[e]; }
        const float inv = 1.f / s;
#pragma unroll
        for (int e = 0; e < 64; e++) p[e] *= inv;

        const int gtok = tokBase + t;
        unsigned long long chosen = 0ull;
        float tv[5]; int tix[5];
#pragma unroll
        for (int r = 0; r < 5; r++) {
            float bv = -1.f; int bi = 0;
#pragma unroll
            for (int e = 0; e < 64; e++) {
                bool skip = (chosen >> e) & 1ull;
                if (!skip && p[e] > bv) { bv = p[e]; bi = e; }  // strict >: lowest idx ties
            }
            chosen |= 1ull << bi;
            tv[r] = bv; tix[r] = bi;
        }
#pragma unroll
        for (int r = 0; r < TOP_K; r++) {
            out_idx[(size_t)gtok * TOP_K + r] = (float)tix[r];
            out_val[(size_t)gtok * TOP_K + r] = tv[r];
        }
        // near-tie among ranks 1..5 -> queue exact repair
        float ming = tv[0] - tv[1];
        ming = fminf(ming, tv[1] - tv[2]);
        ming = fminf(ming, tv[2] - tv[3]);
        ming = fminf(ming, tv[3] - tv[4]);
        if (ming < GAP_EPS) {
            int pos = atomicAdd(&g_count, 1);
            if (pos < MAXREP) g_repair[pos] = gtok;
        }
#pragma unroll
        for (int e = 0; e < 64; e++) L[t * 65 + e] = p[e];
    }
    __syncthreads();

    for (int i = tid; i < TM * NUM_EXPERTS; i += 256) {
        int t = i >> 6, e = i & 63;
        out_scores[(size_t)(tokBase + t) * NUM_EXPERTS + e] = L[t * 65 + e];
    }
    if (tid < NUM_EXPERTS) {
        float s = 0.f;
#pragma unroll 8
        for (int t = 0; t < TM; t++) s += L[t * 65 + tid];
        g_expert_partial[(size_t)blockIdx.x * NUM_EXPERTS + tid] = s;
    }
}

// ================= exact repair: sequential fp32 chain (R1-equivalent) ======
__global__ void __launch_bounds__(64) repair_kernel(
    const float* __restrict__ u, const float* __restrict__ E,
    const float* __restrict__ bias,
    float* __restrict__ out_idx, float* __restrict__ out_val,
    float* __restrict__ out_scores)
{
    __shared__ float P[64];
    const int e = threadIdx.x;   // one expert per thread
    int nrep = g_count; if (nrep > MAXREP) nrep = MAXREP;

    for (int item = blockIdx.x; item < nrep; item += gridDim.x) {
        const int tok = g_repair[item];
        const float* ur = u + (size_t)tok * D_MODEL;
        float acc = 0.f;   // single sequential FMA chain over k (matches reference class)
#pragma unroll 8
        for (int k = 0; k < D_MODEL; k++)
            acc = fmaf(ur[k], E[(size_t)k * NUM_EXPERTS + e], acc);
        P[e] = acc + bias[e];
        __syncthreads();

        if (e == 0) {
            float p[64];
            float mx = -1e30f;
#pragma unroll
            for (int i = 0; i < 64; i++) { p[i] = P[i]; mx = fmaxf(mx, p[i]); }
            float s = 0.f;
#pragma unroll
            for (int i = 0; i < 64; i++) { p[i] = expf(p[i] - mx); s += p[i]; }
            const float inv = 1.f / s;
#pragma unroll
            for (int i = 0; i < 64; i++) p[i] *= inv;
#pragma unroll
            for (int i = 0; i < 64; i++) P[i] = p[i];

            unsigned long long chosen = 0ull;
#pragma unroll
            for (int r = 0; r < TOP_K; r++) {
                float bv = -1.f; int bi = 0;
#pragma unroll
                for (int i = 0; i < 64; i++) {
                    bool skip = (chosen >> i) & 1ull;
                    if (!skip && p[i] > bv) { bv = p[i]; bi = i; }
                }
                chosen |= 1ull << bi;
                out_idx[(size_t)tok * TOP_K + r] = (float)bi;
                out_val[(size_t)tok * TOP_K + r] = bv;
            }
        }
        __syncthreads();
        out_scores[(size_t)tok * NUM_EXPERTS + e] = P[e];
        __syncthreads();
    }
}

// ================= aux loss reduction =======================================
__global__ void aux_kernel(float* __restrict__ out_aux) {
    __shared__ float red[64][17];
    __shared__ float sq[64];
    const int tid = threadIdx.x;           // 1024 threads
    const int e = tid >> 4, j = tid & 15;
    float s = 0.f;
#pragma unroll
    for (int i = 0; i < 8; i++)
        s += g_expert_partial[(size_t)(j + 16 * i) * NUM_EXPERTS + e];
    red[e][j] = s;
    __syncthreads();
    if (tid < 64) {
        float t = 0.f;
#pragma unroll
        for (int k = 0; k < 16; k++) t += red[tid][k];
        float m = t * (1.f / (float)N_TOKENS);
        sq[tid] = m * m;
    }
    __syncthreads();
    if (tid == 0) {
        float a = 0.f;
#pragma unroll
        for (int k = 0; k < 64; k++) a += sq[k];
        out_aux[0] = a * (float)NUM_EXPERTS;
    }
}

// ================= launch ===================================================
extern "C" void kernel_launch(void* const* d_in, const int* in_sizes, int n_in,
                              void* d_out, int out_size)
{
    const float* u    = (const float*)d_in[0];
    const float* E    = (const float*)d_in[1];
    const float* bias = (const float*)d_in[2];

    float* out        = (float*)d_out;
    float* out_idx    = out;
    float* out_val    = out_idx + (size_t)N_TOKENS * TOP_K;
    float* out_scores = out_val + (size_t)N_TOKENS * TOP_K;
    float* out_aux    = out_scores + (size_t)N_TOKENS * NUM_EXPERTS;

    cudaFuncSetAttribute(router_kernel, cudaFuncAttributeMaxDynamicSharedMemorySize, SM_TOTAL);

    prep_E<<<D_MODEL / 64, 256>>>(E);
    router_kernel<<<NBLK, 256, SM_TOTAL>>>(u, bias, out_idx, out_val, out_scores);
    repair_kernel<<<256, 64>>>(u, E, bias, out_idx, out_val, out_scores);
    aux_kernel<<<1, 1024>>>(out_aux);
}

// round 5
// speedup vs baseline: 1.5548x; 1.5548x over previous
#include <cuda_runtime.h>
#include <cstdint>

#define D_MODEL     2048
#define NUM_EXPERTS 64
#define NPAIR       32
#define TOP_K       4
#define TM          128              // tokens per CTA
#define KC          32               // K chunk
#define NCHUNK      (D_MODEL / KC)   // 64
#define N_TOKENS    16384
#define NBLK        (N_TOKENS / TM)  // 128

// ---- dynamic smem layout (bytes) ----
#define A_STRIDE_W 36                                  // words per token row (16B-aligned, conflict-free)
#define A_STAGE    (TM * A_STRIDE_W * 4)               // 18432
#define B_STRIDE_W 68                                  // words per pair row (16B-aligned, conflict-free)
#define B_STAGE    (NPAIR * B_STRIDE_W * 4)            // 8704
#define SM_A       0                                   // 2 stages
#define SM_B       (2 * A_STAGE)                       // 36864
#define SM_BIAS    (SM_B + 2 * B_STAGE)                // 54272
#define SM_TOTAL   (SM_BIAS + 256)                     // 54528
// epilogue L[128][65] floats = 33280 B reuses the A region

// ---- device scratch ----
__device__ float g_expert_partial[NBLK * NUM_EXPERTS];
__device__ float g_Ep[NPAIR * D_MODEL * 2];   // [pair][k][2] interleaved expert pairs

// ================= helpers ==================================================
__device__ __forceinline__ uint32_t smem_to_u32(const void* p) {
    uint32_t a;
    asm("{ .reg .u64 t; cvta.to.shared.u64 t, %1; cvt.u32.u64 %0, t; }" : "=r"(a) : "l"(p));
    return a;
}
#define CP_ASYNC16(dst_u32, src_ptr) \
    asm volatile("cp.async.cg.shared.global [%0], [%1], 16;" :: "r"(dst_u32), "l"(src_ptr))
#define CP_COMMIT() asm volatile("cp.async.commit_group;" ::: "memory")
#define CP_WAIT1()  asm volatile("cp.async.wait_group 1;" ::: "memory")
#define CP_WAIT0()  asm volatile("cp.async.wait_group 0;" ::: "memory")

// packed fp32x2 fma: d = a*b + d elementwise on 2xfp32 (Blackwell FFMA2 path)
__device__ __forceinline__ void fma2(unsigned long long& d, unsigned long long a, unsigned long long b) {
    asm("fma.rn.f32x2 %0, %1, %2, %0;" : "+l"(d) : "l"(a), "l"(b));
}
__device__ __forceinline__ unsigned long long dup2(float x) {
    unsigned long long r;
    uint32_t xb = __float_as_uint(x);
    asm("mov.b64 %0, {%1, %1};" : "=l"(r) : "r"(xb));
    return r;
}
__device__ __forceinline__ void unpack2(unsigned long long v, float& lo, float& hi) {
    uint32_t l, h;
    asm("mov.b64 {%0, %1}, %2;" : "=r"(l), "=r"(h) : "l"(v));
    lo = __uint_as_float(l); hi = __uint_as_float(h);
}

// ================= prep: E[2048][64] -> g_Ep[pair][k][2] ====================
__global__ void prep_E(const float* __restrict__ E) {
    const int tid = threadIdx.x;
    const int k0 = blockIdx.x * 64;
#pragma unroll
    for (int i = 0; i < 16; i++) {
        int idx = tid + i * 256;
        int k = k0 + (idx >> 6), e = idx & 63;
        g_Ep[(size_t)(e >> 1) * (D_MODEL * 2) + k * 2 + (e & 1)] = E[(size_t)k * NUM_EXPERTS + e];
    }
}

// ================= main fused router (FFMA2 SIMT) ===========================
__global__ void __launch_bounds__(256) router_kernel(
    const float* __restrict__ u, const float* __restrict__ bias,
    float* __restrict__ out_idx, float* __restrict__ out_val,
    float* __restrict__ out_scores)
{
    extern __shared__ char smem[];
    const uint32_t sb = smem_to_u32(smem);
    const int tid = threadIdx.x, wid = tid >> 5, lid = tid & 31;
    const int tg = lid >> 3, eg = lid & 7;     // token-group / expert-group in warp
    const int tokBase = blockIdx.x * TM;

    if (tid < NUM_EXPERTS) ((float*)(smem + SM_BIAS))[tid] = bias[tid];

    // ---- async-copy issue for chunk c ----
    const int urow = tid >> 3;      // 0..31
    const int uc4  = tid & 7;       // float4 within 32-float k-chunk
    auto issue = [&](int c) {
        const int st = c & 1;
        const int k0 = c * KC;
        const uint32_t ab = sb + SM_A + st * A_STAGE;
        const uint32_t bb = sb + SM_B + st * B_STAGE;
#pragma unroll
        for (int i = 0; i < 4; i++) {
            int row = urow + i * 32;
            CP_ASYNC16(ab + (uint32_t)(row * (A_STRIDE_W * 4) + uc4 * 16),
                       u + (size_t)(tokBase + row) * D_MODEL + k0 + uc4 * 4);
        }
        // B: 512 x 16B units; 2 per thread. unit q: pair=q>>4, kq=q&15 (2 k's per unit)
#pragma unroll
        for (int i = 0; i < 2; i++) {
            int q = tid + i * 256;
            int pr = q >> 4, kq = q & 15;
            CP_ASYNC16(bb + (uint32_t)(pr * (B_STRIDE_W * 4) + kq * 16),
                       g_Ep + (size_t)pr * (D_MODEL * 2) + k0 * 2 + kq * 4);
        }
        CP_COMMIT();
    };

    unsigned long long acc[4][4];   // [token i][pair j], f32x2 (lo=expert 2p, hi=2p+1)
#pragma unroll
    for (int i = 0; i < 4; i++)
#pragma unroll
        for (int j = 0; j < 4; j++) acc[i][j] = 0ull;

    issue(0);
    issue(1);

    for (int c = 0; c < NCHUNK; c++) {
        if (c < NCHUNK - 1) CP_WAIT1(); else CP_WAIT0();
        __syncthreads();

        const int st = c & 1;
        const float* as = (const float*)(smem + SM_A + st * A_STAGE);
        const unsigned long long* bs = (const unsigned long long*)(smem + SM_B + st * B_STAGE);

#pragma unroll 8
        for (int kk = 0; kk < KC; kk++) {
            unsigned long long av[4], bv[4];
#pragma unroll
            for (int i = 0; i < 4; i++)
                av[i] = dup2(as[(wid * 16 + tg + 4 * i) * A_STRIDE_W + kk]);
#pragma unroll
            for (int j = 0; j < 4; j++)
                bv[j] = bs[(eg + 8 * j) * (B_STRIDE_W / 2) + kk];
#pragma unroll
            for (int i = 0; i < 4; i++)
#pragma unroll
                for (int j = 0; j < 4; j++)
                    fma2(acc[i][j], av[i], bv[j]);
        }
        __syncthreads();
        if (c + 2 < NCHUNK) issue(c + 2);
    }

    // ---- epilogue: acc -> smem L[128][65], then per-token softmax + top-4 ----
    float* L = (float*)(smem + SM_A);   // 33280 B < 36864 B (A region)
#pragma unroll
    for (int i = 0; i < 4; i++) {
        const int t = wid * 16 + tg + 4 * i;
#pragma unroll
        for (int j = 0; j < 4; j++) {
            const int p = eg + 8 * j;
            float lo, hi;
            unpack2(acc[i][j], lo, hi);
            L[t * 65 + 2 * p]     = lo;
            L[t * 65 + 2 * p + 1] = hi;
        }
    }
    __syncthreads();

    const float* biasS = (const float*)(smem + SM_BIAS);
    if (tid < TM) {
        const int t = tid;
        float p[64];
        float mx = -1e30f;
#pragma unroll
        for (int e = 0; e < 64; e++) { p[e] = L[t * 65 + e] + biasS[e]; mx = fmaxf(mx, p[e]); }
        float s = 0.f;
#pragma unroll
        for (int e = 0; e < 64; e++) { p[e] = expf(p[e] - mx); s += p[e]; }
        const float inv = 1.f / s;
#pragma unroll
        for (int e = 0; e < 64; e++) p[e] *= inv;

        const int gtok = tokBase + t;
        unsigned long long chosen = 0ull;
#pragma unroll
        for (int r = 0; r < TOP_K; r++) {
            float bv = -1.f; int bi = 0;
#pragma unroll
            for (int e = 0; e < 64; e++) {
                bool skip = (chosen >> e) & 1ull;
                if (!skip && p[e] > bv) { bv = p[e]; bi = e; }  // strict >: lowest idx ties
            }
            chosen |= 1ull << bi;
            out_idx[(size_t)gtok * TOP_K + r] = (float)bi;
            out_val[(size_t)gtok * TOP_K + r] = bv;
        }
#pragma unroll
        for (int e = 0; e < 64; e++) L[t * 65 + e] = p[e];
    }
    __syncthreads();

    // coalesced scores writeback
    for (int i = tid; i < TM * NUM_EXPERTS; i += 256) {
        int t = i >> 6, e = i & 63;
        out_scores[(size_t)(tokBase + t) * NUM_EXPERTS + e] = L[t * 65 + e];
    }
    // deterministic per-block expert sums
    if (tid < NUM_EXPERTS) {
        float s = 0.f;
#pragma unroll 8
        for (int t = 0; t < TM; t++) s += L[t * 65 + tid];
        g_expert_partial[(size_t)blockIdx.x * NUM_EXPERTS + tid] = s;
    }
}

// ================= aux loss reduction =======================================
__global__ void aux_kernel(float* __restrict__ out_aux) {
    __shared__ float red[64][17];
    __shared__ float sq[64];
    const int tid = threadIdx.x;           // 1024 threads
    const int e = tid >> 4, j = tid & 15;
    float s = 0.f;
#pragma unroll
    for (int i = 0; i < 8; i++)
        s += g_expert_partial[(size_t)(j + 16 * i) * NUM_EXPERTS + e];
    red[e][j] = s;
    __syncthreads();
    if (tid < 64) {
        float t = 0.f;
#pragma unroll
        for (int k = 0; k < 16; k++) t += red[tid][k];
        float m = t * (1.f / (float)N_TOKENS);
        sq[tid] = m * m;
    }
    __syncthreads();
    if (tid == 0) {
        float a = 0.f;
#pragma unroll
        for (int k = 0; k < 64; k++) a += sq[k];
        out_aux[0] = a * (float)NUM_EXPERTS;
    }
}

// ================= launch ===================================================
extern "C" void kernel_launch(void* const* d_in, const int* in_sizes, int n_in,
                              void* d_out, int out_size)
{
    const float* u    = (const float*)d_in[0];
    const float* E    = (const float*)d_in[1];
    const float* bias = (const float*)d_in[2];

    float* out        = (float*)d_out;
    float* out_idx    = out;
    float* out_val    = out_idx + (size_t)N_TOKENS * TOP_K;
    float* out_scores = out_val + (size_t)N_TOKENS * TOP_K;
    float* out_aux    = out_scores + (size_t)N_TOKENS * NUM_EXPERTS;

    cudaFuncSetAttribute(router_kernel, cudaFuncAttributeMaxDynamicSharedMemorySize, SM_TOTAL);

    prep_E<<<D_MODEL / 64, 256>>>(E);
    router_kernel<<<NBLK, 256, SM_TOTAL>>>(u, bias, out_idx, out_val, out_scores);
    aux_kernel<<<1, 1024>>>(out_aux);
}